// round 10
// baseline (speedup 1.0000x reference)
#include <cuda_runtime.h>

// Problem constants
#define Nn   4
#define Pp   2048
#define Dd   512
#define Hh   8
#define HDim 64
#define NB   (Nn * Hh)                   // 32 batched (n,h) heads
#define NCH  16                          // 2048/128 col chunks in qk
#define SCALE 0.044194173824159216f      // 1/sqrt(512)

// ---------------------------------------------------------------------------
// Device scratch
// ---------------------------------------------------------------------------
__device__ float g_Q[(size_t)NB * Pp * HDim];
__device__ float g_K[(size_t)NB * Pp * HDim];
__device__ float g_V[(size_t)NB * Pp * HDim];
__device__ float g_OVp0[(size_t)Nn * Pp * Dd];        // split-K partial 0
__device__ float g_OVp1[(size_t)Nn * Pp * Dd];        // split-K partial 1
__device__ float g_pstat[(size_t)NB * Pp * NCH * 2];  // per (b,row,chunk): {max, sumexp}
__device__ float g_ms[(size_t)NB * Pp * 2];           // per (b,row): {max, 1/sum}
__device__ float g_attn_fb[(size_t)NB * Pp * Pp];     // fallback attention buffer

// ---------------------------------------------------------------------------
// K1: fused Q/K/V projection (unchanged).
// ---------------------------------------------------------------------------
__global__ void __launch_bounds__(256) qkv_kernel(
    const float* __restrict__ x,
    const float* __restrict__ Wq,
    const float* __restrict__ Wk,
    const float* __restrict__ Wv)
{
    __shared__ float Xs[64][64];
    __shared__ float Ws[64][65];

    const int t  = threadIdx.x;
    const int tx = t & 15;
    const int ty = t >> 4;
    const int r0 = blockIdx.x * 64;

    {
        const float4* src = reinterpret_cast<const float4*>(x) + (size_t)r0 * 16;
        float4* dst = reinterpret_cast<float4*>(&Xs[0][0]);
#pragma unroll
        for (int l = 0; l < 4; l++) dst[t + 256 * l] = src[t + 256 * l];
    }

#pragma unroll 1
    for (int m = 0; m < 3; m++) {
        const float* W = (m == 0) ? Wq : (m == 1) ? Wk : Wv;
        float*       O = (m == 0) ? g_Q : (m == 1) ? g_K : g_V;

        __syncthreads();
#pragma unroll
        for (int l = 0; l < 16; l++) {
            int i = t + 256 * l;
            Ws[i >> 6][i & 63] = W[i];
        }
        __syncthreads();

        float acc[4][4];
#pragma unroll
        for (int i = 0; i < 4; i++)
#pragma unroll
            for (int j = 0; j < 4; j++) acc[i][j] = 0.f;

#pragma unroll 8
        for (int k = 0; k < 64; k++) {
            float a[4], w[4];
#pragma unroll
            for (int i = 0; i < 4; i++) a[i] = Xs[ty + 16 * i][k];
#pragma unroll
            for (int j = 0; j < 4; j++) w[j] = Ws[tx + 16 * j][k];
#pragma unroll
            for (int i = 0; i < 4; i++)
#pragma unroll
                for (int j = 0; j < 4; j++) acc[i][j] = fmaf(a[i], w[j], acc[i][j]);
        }

#pragma unroll
        for (int i = 0; i < 4; i++) {
            int r = r0 + ty + 16 * i;
            int h = r & 7;
            int p = (r >> 3) & (Pp - 1);
            int n = r >> 14;
            float* dst = O + ((size_t)(n * Hh + h) * Pp + p) * HDim;
#pragma unroll
            for (int j = 0; j < 4; j++) dst[tx + 16 * j] = acc[i][j];
        }
    }
}

// ---------------------------------------------------------------------------
// K2: energy e = (SCALE*Q) @ K^T, then IN REGISTERS: per-(row,chunk) max m,
// p_unnorm = exp(e - m), partial sum s. Stores p_unnorm to attn and {m,s}
// to g_pstat. Exp amortized here: 64 exps vs 4096 FMAs per thread.
// ---------------------------------------------------------------------------
__global__ void __launch_bounds__(256) qk_kernel(float* __restrict__ attn)
{
    __shared__ float Qs[32][128];   // [k][m]
    __shared__ float Ks[32][128];   // [k][n]

    const int t    = threadIdx.x;
    const int tx   = t & 15;
    const int ty   = t >> 4;
    const int row  = t & 127;
    const int half = t >> 7;
    const int b    = blockIdx.z;
    const int m0   = blockIdx.y * 128;
    const int n0   = blockIdx.x * 128;

    const float* Qg = g_Q + (size_t)b * Pp * HDim + (size_t)(m0 + row) * HDim + half * 16;
    const float* Kg = g_K + (size_t)b * Pp * HDim + (size_t)(n0 + row) * HDim + half * 16;

    float acc[8][8];
#pragma unroll
    for (int i = 0; i < 8; i++)
#pragma unroll
        for (int j = 0; j < 8; j++) acc[i][j] = 0.f;

#pragma unroll 1
    for (int kc = 0; kc < HDim; kc += 32) {
        __syncthreads();
#pragma unroll
        for (int j = 0; j < 4; j++) {
            float4 q4 = *reinterpret_cast<const float4*>(Qg + kc + j * 4);
            float4 k4 = *reinterpret_cast<const float4*>(Kg + kc + j * 4);
            int kk = half * 16 + j * 4;
            Qs[kk + 0][row] = q4.x * SCALE; Qs[kk + 1][row] = q4.y * SCALE;
            Qs[kk + 2][row] = q4.z * SCALE; Qs[kk + 3][row] = q4.w * SCALE;
            Ks[kk + 0][row] = k4.x; Ks[kk + 1][row] = k4.y;
            Ks[kk + 2][row] = k4.z; Ks[kk + 3][row] = k4.w;
        }
        __syncthreads();

#pragma unroll 16
        for (int k = 0; k < 32; k++) {
            float4 a0 = *reinterpret_cast<const float4*>(&Qs[k][ty * 4]);
            float4 a1 = *reinterpret_cast<const float4*>(&Qs[k][ty * 4 + 64]);
            float4 b0 = *reinterpret_cast<const float4*>(&Ks[k][tx * 4]);
            float4 b1 = *reinterpret_cast<const float4*>(&Ks[k][tx * 4 + 64]);
            float a[8]  = {a0.x, a0.y, a0.z, a0.w, a1.x, a1.y, a1.z, a1.w};
            float bb[8] = {b0.x, b0.y, b0.z, b0.w, b1.x, b1.y, b1.z, b1.w};
#pragma unroll
            for (int i = 0; i < 8; i++)
#pragma unroll
                for (int j = 0; j < 8; j++) acc[i][j] = fmaf(a[i], bb[j], acc[i][j]);
        }
    }

    float* dst = attn + (size_t)b * Pp * Pp;
#pragma unroll
    for (int i = 0; i < 8; i++) {
        const int r = m0 + ty * 4 + (i & 3) + (i >> 2) * 64;

        // chunk-row max over the 128 cols held by the 16 tx-lanes of this ty
        float m_l = acc[i][0];
#pragma unroll
        for (int j = 1; j < 8; j++) m_l = fmaxf(m_l, acc[i][j]);
#pragma unroll
        for (int o = 8; o > 0; o >>= 1)
            m_l = fmaxf(m_l, __shfl_xor_sync(0xffffffffu, m_l, o));

        // exp in place + partial sum
        float s_l = 0.f;
#pragma unroll
        for (int j = 0; j < 8; j++) {
            acc[i][j] = __expf(acc[i][j] - m_l);
            s_l += acc[i][j];
        }
#pragma unroll
        for (int o = 8; o > 0; o >>= 1)
            s_l += __shfl_xor_sync(0xffffffffu, s_l, o);

        if (tx == 0) {
            float2* ps = reinterpret_cast<float2*>(g_pstat)
                       + ((size_t)b * Pp + r) * NCH + blockIdx.x;
            *ps = make_float2(m_l, s_l);
        }

        float4 v0 = {acc[i][0], acc[i][1], acc[i][2], acc[i][3]};
        float4 v1 = {acc[i][4], acc[i][5], acc[i][6], acc[i][7]};
        *reinterpret_cast<float4*>(dst + (size_t)r * Pp + n0 + tx * 4)      = v0;
        *reinterpret_cast<float4*>(dst + (size_t)r * Pp + n0 + tx * 4 + 64) = v1;
    }
}

// ---------------------------------------------------------------------------
// K3: merge 16 chunk partials per row -> {max, 1/sum}. 65536 rows.
// ---------------------------------------------------------------------------
__global__ void __launch_bounds__(256) stat_reduce_kernel()
{
    const int r = blockIdx.x * 256 + threadIdx.x;
    const float2* ps = reinterpret_cast<const float2*>(g_pstat) + (size_t)r * NCH;
    float m = -1e30f, s = 0.f;
#pragma unroll
    for (int c = 0; c < NCH; c++) {
        float2 v = ps[c];
        float mn = fmaxf(m, v.x);
        s = s * __expf(m - mn) + v.y * __expf(v.x - mn);
        m = mn;
    }
    reinterpret_cast<float2*>(g_ms)[r] = make_float2(m, 1.0f / s);
}

// ---------------------------------------------------------------------------
// K4: fused rescale + AV, split-K=2. Reads p_unnorm, applies per-chunk scalar
// f = exp(m_chunk - M)/S (ONE exp per 128 cols), writes normalized attention
// in place, accumulates p@V into split-K partial g_OVp{0,1}.
// 128x64 tile, 128 threads, 8x8/thread, double-buffered smem.
// ---------------------------------------------------------------------------
__global__ void __launch_bounds__(128, 8) sav_kernel(float* __restrict__ attn)
{
    __shared__ float As[2][16][128];   // [buf][k][m]
    __shared__ float Vs[2][16][64];    // [buf][k][n]

    const int t    = threadIdx.x;
    const int tx   = t & 7;
    const int ty   = t >> 3;
    const int b    = blockIdx.y;
    const int m0   = blockIdx.x * 128;
    const int z    = blockIdx.z;           // split-K half
    const int kbeg = z * (Pp / 2);
    const int kend = kbeg + (Pp / 2);

    float* Arow = attn + (size_t)b * Pp * Pp + (size_t)(m0 + t) * Pp;
    const float* Vg = g_V + (size_t)b * Pp * HDim;
    const float2* prow = reinterpret_cast<const float2*>(g_pstat)
                       + ((size_t)b * Pp + m0 + t) * NCH;

    const float2 ms = reinterpret_cast<const float2*>(g_ms)[(size_t)b * Pp + m0 + t];
    const float myM = ms.x;
    const float myI = ms.y;

    const int vk0 = t >> 4,         vc0 = (t & 15) * 4;
    const int vk1 = (t + 128) >> 4, vc1 = ((t + 128) & 15) * 4;

    float acc[8][8];
#pragma unroll
    for (int i = 0; i < 8; i++)
#pragma unroll
        for (int j = 0; j < 8; j++) acc[i][j] = 0.f;

    float4 ra[4], rv0, rv1;
#pragma unroll
    for (int j = 0; j < 4; j++)
        ra[j] = *reinterpret_cast<const float4*>(Arow + kbeg + j * 4);
    rv0 = *reinterpret_cast<const float4*>(Vg + (size_t)(kbeg + vk0) * HDim + vc0);
    rv1 = *reinterpret_cast<const float4*>(Vg + (size_t)(kbeg + vk1) * HDim + vc1);

    // Fill stage 0
    {
        float2 pc = prow[kbeg >> 7];
        float f = __expf(pc.x - myM) * myI;
#pragma unroll
        for (int j = 0; j < 4; j++) {
            float4 p = {ra[j].x * f, ra[j].y * f, ra[j].z * f, ra[j].w * f};
            As[0][j * 4 + 0][t] = p.x; As[0][j * 4 + 1][t] = p.y;
            As[0][j * 4 + 2][t] = p.z; As[0][j * 4 + 3][t] = p.w;
            *reinterpret_cast<float4*>(Arow + kbeg + j * 4) = p;
        }
    }
    *reinterpret_cast<float4*>(&Vs[0][vk0][vc0]) = rv0;
    *reinterpret_cast<float4*>(&Vs[0][vk1][vc1]) = rv1;
    __syncthreads();

    int buf = 0;
#pragma unroll 1
    for (int kc = kbeg; kc < kend; kc += 16) {
        const bool more = (kc + 16 < kend);
        if (more) {   // prefetch next stage into registers
#pragma unroll
            for (int j = 0; j < 4; j++)
                ra[j] = *reinterpret_cast<const float4*>(Arow + kc + 16 + j * 4);
            rv0 = *reinterpret_cast<const float4*>(Vg + (size_t)(kc + 16 + vk0) * HDim + vc0);
            rv1 = *reinterpret_cast<const float4*>(Vg + (size_t)(kc + 16 + vk1) * HDim + vc1);
        }

#pragma unroll
        for (int k = 0; k < 16; k++) {
            float4 a0 = *reinterpret_cast<const float4*>(&As[buf][k][ty * 4]);
            float4 a1 = *reinterpret_cast<const float4*>(&As[buf][k][ty * 4 + 64]);
            float4 v0 = *reinterpret_cast<const float4*>(&Vs[buf][k][tx * 4]);
            float4 v1 = *reinterpret_cast<const float4*>(&Vs[buf][k][tx * 4 + 32]);
            float a[8] = {a0.x, a0.y, a0.z, a0.w, a1.x, a1.y, a1.z, a1.w};
            float v[8] = {v0.x, v0.y, v0.z, v0.w, v1.x, v1.y, v1.z, v1.w};
#pragma unroll
            for (int i = 0; i < 8; i++)
#pragma unroll
                for (int j = 0; j < 8; j++) acc[i][j] = fmaf(a[i], v[j], acc[i][j]);
        }

        if (more) {
            const int nb = buf ^ 1;
            float2 pc = prow[(kc + 16) >> 7];
            float f = __expf(pc.x - myM) * myI;
#pragma unroll
            for (int j = 0; j < 4; j++) {
                float4 p = {ra[j].x * f, ra[j].y * f, ra[j].z * f, ra[j].w * f};
                As[nb][j * 4 + 0][t] = p.x; As[nb][j * 4 + 1][t] = p.y;
                As[nb][j * 4 + 2][t] = p.z; As[nb][j * 4 + 3][t] = p.w;
                *reinterpret_cast<float4*>(Arow + kc + 16 + j * 4) = p;
            }
            *reinterpret_cast<float4*>(&Vs[nb][vk0][vc0]) = rv0;
            *reinterpret_cast<float4*>(&Vs[nb][vk1][vc1]) = rv1;
        }
        __syncthreads();
        buf ^= 1;
    }

    float* OVp = (z == 0) ? g_OVp0 : g_OVp1;
    const int n = b >> 3, h = b & 7;
#pragma unroll
    for (int i = 0; i < 8; i++) {
        int p = m0 + ty * 4 + (i & 3) + (i >> 2) * 64;
        float* dst = OVp + ((size_t)n * Pp + p) * Dd + h * HDim;
        float4 w0 = {acc[i][0], acc[i][1], acc[i][2], acc[i][3]};
        float4 w1 = {acc[i][4], acc[i][5], acc[i][6], acc[i][7]};
        *reinterpret_cast<float4*>(dst + tx * 4)      = w0;
        *reinterpret_cast<float4*>(dst + tx * 4 + 32) = w1;
    }
}

// ---------------------------------------------------------------------------
// K5: out = (OVp0+OVp1) @ Wo^T + bo. Split-K partials summed during load.
// ---------------------------------------------------------------------------
__global__ void __launch_bounds__(256) wo_kernel(
    float* __restrict__ out,
    const float* __restrict__ Wo,
    const float* __restrict__ bo)
{
    __shared__ float Xs[16][128];
    __shared__ float Ws[16][128];

    const int t   = threadIdx.x;
    const int tx  = t & 15;
    const int ty  = t >> 4;
    const int m0  = blockIdx.y * 128;
    const int n0  = blockIdx.x * 128;
    const int lr  = t & 127;
    const bool isX = (t < 128);

    const float* srcA = isX ? g_OVp0 + (size_t)(m0 + lr) * Dd
                            : Wo     + (size_t)(n0 + lr) * Dd;
    const float* srcB = g_OVp1 + (size_t)(m0 + lr) * Dd;   // used only when isX
    float (*S)[128] = isX ? Xs : Ws;

    float acc[8][8];
#pragma unroll
    for (int i = 0; i < 8; i++)
#pragma unroll
        for (int j = 0; j < 8; j++) acc[i][j] = 0.f;

    float4 rg[4];
#pragma unroll
    for (int j = 0; j < 4; j++) {
        rg[j] = *reinterpret_cast<const float4*>(srcA + j * 4);
        if (isX) {
            float4 e = *reinterpret_cast<const float4*>(srcB + j * 4);
            rg[j].x += e.x; rg[j].y += e.y; rg[j].z += e.z; rg[j].w += e.w;
        }
    }

#pragma unroll 1
    for (int kc = 0; kc < Dd; kc += 16) {
#pragma unroll
        for (int j = 0; j < 4; j++) {
            S[j * 4 + 0][lr] = rg[j].x; S[j * 4 + 1][lr] = rg[j].y;
            S[j * 4 + 2][lr] = rg[j].z; S[j * 4 + 3][lr] = rg[j].w;
        }
        __syncthreads();

        if (kc + 16 < Dd) {
#pragma unroll
            for (int j = 0; j < 4; j++) {
                rg[j] = *reinterpret_cast<const float4*>(srcA + kc + 16 + j * 4);
                if (isX) {
                    float4 e = *reinterpret_cast<const float4*>(srcB + kc + 16 + j * 4);
                    rg[j].x += e.x; rg[j].y += e.y; rg[j].z += e.z; rg[j].w += e.w;
                }
            }
        }

#pragma unroll
        for (int k = 0; k < 16; k++) {
            float4 a0 = *reinterpret_cast<const float4*>(&Xs[k][ty * 4]);
            float4 a1 = *reinterpret_cast<const float4*>(&Xs[k][ty * 4 + 64]);
            float4 w0 = *reinterpret_cast<const float4*>(&Ws[k][tx * 4]);
            float4 w1 = *reinterpret_cast<const float4*>(&Ws[k][tx * 4 + 64]);
            float a[8] = {a0.x, a0.y, a0.z, a0.w, a1.x, a1.y, a1.z, a1.w};
            float w[8] = {w0.x, w0.y, w0.z, w0.w, w1.x, w1.y, w1.z, w1.w};
#pragma unroll
            for (int i = 0; i < 8; i++)
#pragma unroll
                for (int j = 0; j < 8; j++) acc[i][j] = fmaf(a[i], w[j], acc[i][j]);
        }
        __syncthreads();
    }

    float bv[8];
#pragma unroll
    for (int j = 0; j < 8; j++)
        bv[j] = bo[n0 + tx * 4 + (j & 3) + (j >> 2) * 64];

#pragma unroll
    for (int i = 0; i < 8; i++) {
        int r = m0 + ty * 4 + (i & 3) + (i >> 2) * 64;
        float4 w0 = {acc[i][0] + bv[0], acc[i][1] + bv[1], acc[i][2] + bv[2], acc[i][3] + bv[3]};
        float4 w1 = {acc[i][4] + bv[4], acc[i][5] + bv[5], acc[i][6] + bv[6], acc[i][7] + bv[7]};
        *reinterpret_cast<float4*>(out + (size_t)r * Dd + n0 + tx * 4)      = w0;
        *reinterpret_cast<float4*>(out + (size_t)r * Dd + n0 + tx * 4 + 64) = w1;
    }
}

// ---------------------------------------------------------------------------
// Launch
// ---------------------------------------------------------------------------
extern "C" void kernel_launch(void* const* d_in, const int* in_sizes, int n_in,
                              void* d_out, int out_size)
{
    const float* xyz = (const float*)d_in[0];
    const float* Wq  = (const float*)d_in[1];
    const float* Wk  = (const float*)d_in[2];
    const float* Wv  = (const float*)d_in[3];
    const float* Wo  = (const float*)d_in[4];
    const float* bo  = (const float*)d_in[5];
    float* out = (float*)d_out;

    const size_t OUT_E  = (size_t)Nn * Pp * Dd;
    const size_t ATTN_E = (size_t)NB * Pp * Pp;

    float* attn;
    if ((size_t)out_size >= OUT_E + ATTN_E) {
        attn = out + OUT_E;
    } else {
        void* p = nullptr;
        cudaGetSymbolAddress(&p, g_attn_fb);
        attn = (float*)p;
    }

    qkv_kernel<<<(Nn * Pp * Hh) / 64, 256>>>(xyz, Wq, Wk, Wv);

    dim3 g2(Pp / 128, Pp / 128, NB);          // (16,16,32)
    qk_kernel<<<g2, 256>>>(attn);

    stat_reduce_kernel<<<(NB * Pp) / 256, 256>>>();

    dim3 g4(Pp / 128, NB, 2);                 // (16,32,2) split-K
    sav_kernel<<<g4, 128>>>(attn);

    dim3 g5(Dd / 128, (Nn * Pp) / 128);       // (4,64)
    wo_kernel<<<g5, 256>>>(out, Wo, bo);
}

// round 12
// speedup vs baseline: 3.1145x; 3.1145x over previous
#include <cuda_runtime.h>

// Problem constants
#define Nn   4
#define Pp   2048
#define Dd   512
#define Hh   8
#define HDim 64
#define NB   (Nn * Hh)                   // 32 batched (n,h) heads
#define NCH  16                          // 2048/128 col chunks in qk
#define SCALE 0.044194173824159216f      // 1/sqrt(512)

// ---------------------------------------------------------------------------
// Device scratch
// ---------------------------------------------------------------------------
__device__ float g_Q[(size_t)NB * Pp * HDim];
__device__ float g_K[(size_t)NB * Pp * HDim];
__device__ float g_V[(size_t)NB * Pp * HDim];
__device__ float g_OVp0[(size_t)Nn * Pp * Dd];        // split-K partial 0
__device__ float g_OVp1[(size_t)Nn * Pp * Dd];        // split-K partial 1
__device__ float g_pstat[(size_t)NB * Pp * NCH * 2];  // per (b,row,chunk): {max, sumexp}
__device__ float g_ms[(size_t)NB * Pp * 2];           // per (b,row): {max, 1/sum}
__device__ float g_attn_fb[(size_t)NB * Pp * Pp];     // fallback attention buffer

// ---------------------------------------------------------------------------
// K1: fused Q/K/V projection.
// ---------------------------------------------------------------------------
__global__ void __launch_bounds__(256) qkv_kernel(
    const float* __restrict__ x,
    const float* __restrict__ Wq,
    const float* __restrict__ Wk,
    const float* __restrict__ Wv)
{
    __shared__ float Xs[64][64];
    __shared__ float Ws[64][65];

    const int t  = threadIdx.x;
    const int tx = t & 15;
    const int ty = t >> 4;
    const int r0 = blockIdx.x * 64;

    {
        const float4* src = reinterpret_cast<const float4*>(x) + (size_t)r0 * 16;
        float4* dst = reinterpret_cast<float4*>(&Xs[0][0]);
#pragma unroll
        for (int l = 0; l < 4; l++) dst[t + 256 * l] = src[t + 256 * l];
    }

#pragma unroll 1
    for (int m = 0; m < 3; m++) {
        const float* W = (m == 0) ? Wq : (m == 1) ? Wk : Wv;
        float*       O = (m == 0) ? g_Q : (m == 1) ? g_K : g_V;

        __syncthreads();
#pragma unroll
        for (int l = 0; l < 16; l++) {
            int i = t + 256 * l;
            Ws[i >> 6][i & 63] = W[i];
        }
        __syncthreads();

        float acc[4][4];
#pragma unroll
        for (int i = 0; i < 4; i++)
#pragma unroll
            for (int j = 0; j < 4; j++) acc[i][j] = 0.f;

#pragma unroll 8
        for (int k = 0; k < 64; k++) {
            float a[4], w[4];
#pragma unroll
            for (int i = 0; i < 4; i++) a[i] = Xs[ty + 16 * i][k];
#pragma unroll
            for (int j = 0; j < 4; j++) w[j] = Ws[tx + 16 * j][k];
#pragma unroll
            for (int i = 0; i < 4; i++)
#pragma unroll
                for (int j = 0; j < 4; j++) acc[i][j] = fmaf(a[i], w[j], acc[i][j]);
        }

#pragma unroll
        for (int i = 0; i < 4; i++) {
            int r = r0 + ty + 16 * i;
            int h = r & 7;
            int p = (r >> 3) & (Pp - 1);
            int n = r >> 14;
            float* dst = O + ((size_t)(n * Hh + h) * Pp + p) * HDim;
#pragma unroll
            for (int j = 0; j < 4; j++) dst[tx + 16 * j] = acc[i][j];
        }
    }
}

// ---------------------------------------------------------------------------
// K2: energy e = (SCALE*Q) @ K^T, then IN REGISTERS: per-(row,chunk) max m,
// p_unnorm = exp(e - m), partial sum s. Stores p_unnorm to attn and {m,s}
// to g_pstat. Exp amortized here: 64 exps vs 4096 FMAs per thread.
// ---------------------------------------------------------------------------
__global__ void __launch_bounds__(256) qk_kernel(float* __restrict__ attn)
{
    __shared__ float Qs[32][128];   // [k][m]
    __shared__ float Ks[32][128];   // [k][n]

    const int t    = threadIdx.x;
    const int tx   = t & 15;
    const int ty   = t >> 4;
    const int row  = t & 127;
    const int half = t >> 7;
    const int b    = blockIdx.z;
    const int m0   = blockIdx.y * 128;
    const int n0   = blockIdx.x * 128;

    const float* Qg = g_Q + (size_t)b * Pp * HDim + (size_t)(m0 + row) * HDim + half * 16;
    const float* Kg = g_K + (size_t)b * Pp * HDim + (size_t)(n0 + row) * HDim + half * 16;

    float acc[8][8];
#pragma unroll
    for (int i = 0; i < 8; i++)
#pragma unroll
        for (int j = 0; j < 8; j++) acc[i][j] = 0.f;

#pragma unroll 1
    for (int kc = 0; kc < HDim; kc += 32) {
        __syncthreads();
#pragma unroll
        for (int j = 0; j < 4; j++) {
            float4 q4 = *reinterpret_cast<const float4*>(Qg + kc + j * 4);
            float4 k4 = *reinterpret_cast<const float4*>(Kg + kc + j * 4);
            int kk = half * 16 + j * 4;
            Qs[kk + 0][row] = q4.x * SCALE; Qs[kk + 1][row] = q4.y * SCALE;
            Qs[kk + 2][row] = q4.z * SCALE; Qs[kk + 3][row] = q4.w * SCALE;
            Ks[kk + 0][row] = k4.x; Ks[kk + 1][row] = k4.y;
            Ks[kk + 2][row] = k4.z; Ks[kk + 3][row] = k4.w;
        }
        __syncthreads();

#pragma unroll 16
        for (int k = 0; k < 32; k++) {
            float4 a0 = *reinterpret_cast<const float4*>(&Qs[k][ty * 4]);
            float4 a1 = *reinterpret_cast<const float4*>(&Qs[k][ty * 4 + 64]);
            float4 b0 = *reinterpret_cast<const float4*>(&Ks[k][tx * 4]);
            float4 b1 = *reinterpret_cast<const float4*>(&Ks[k][tx * 4 + 64]);
            float a[8]  = {a0.x, a0.y, a0.z, a0.w, a1.x, a1.y, a1.z, a1.w};
            float bb[8] = {b0.x, b0.y, b0.z, b0.w, b1.x, b1.y, b1.z, b1.w};
#pragma unroll
            for (int i = 0; i < 8; i++)
#pragma unroll
                for (int j = 0; j < 8; j++) acc[i][j] = fmaf(a[i], bb[j], acc[i][j]);
        }
    }

    float* dst = attn + (size_t)b * Pp * Pp;
#pragma unroll
    for (int i = 0; i < 8; i++) {
        const int r = m0 + ty * 4 + (i & 3) + (i >> 2) * 64;

        // chunk-row max over the 128 cols held by the 16 tx-lanes of this ty
        float m_l = acc[i][0];
#pragma unroll
        for (int j = 1; j < 8; j++) m_l = fmaxf(m_l, acc[i][j]);
#pragma unroll
        for (int o = 8; o > 0; o >>= 1)
            m_l = fmaxf(m_l, __shfl_xor_sync(0xffffffffu, m_l, o));

        // exp in place + partial sum
        float s_l = 0.f;
#pragma unroll
        for (int j = 0; j < 8; j++) {
            acc[i][j] = __expf(acc[i][j] - m_l);
            s_l += acc[i][j];
        }
#pragma unroll
        for (int o = 8; o > 0; o >>= 1)
            s_l += __shfl_xor_sync(0xffffffffu, s_l, o);

        if (tx == 0) {
            float2* ps = reinterpret_cast<float2*>(g_pstat)
                       + ((size_t)b * Pp + r) * NCH + blockIdx.x;
            *ps = make_float2(m_l, s_l);
        }

        float4 v0 = {acc[i][0], acc[i][1], acc[i][2], acc[i][3]};
        float4 v1 = {acc[i][4], acc[i][5], acc[i][6], acc[i][7]};
        *reinterpret_cast<float4*>(dst + (size_t)r * Pp + n0 + tx * 4)      = v0;
        *reinterpret_cast<float4*>(dst + (size_t)r * Pp + n0 + tx * 4 + 64) = v1;
    }
}

// ---------------------------------------------------------------------------
// K3: merge 16 chunk partials per row -> {max, 1/sum}. 65536 rows.
// ---------------------------------------------------------------------------
__global__ void __launch_bounds__(256) stat_reduce_kernel()
{
    const int r = blockIdx.x * 256 + threadIdx.x;
    const float2* ps = reinterpret_cast<const float2*>(g_pstat) + (size_t)r * NCH;
    float m = -1e30f, s = 0.f;
#pragma unroll
    for (int c = 0; c < NCH; c++) {
        float2 v = ps[c];
        float mn = fmaxf(m, v.x);
        s = s * __expf(m - mn) + v.y * __expf(v.x - mn);
        m = mn;
    }
    reinterpret_cast<float2*>(g_ms)[r] = make_float2(m, 1.0f / s);
}

// ---------------------------------------------------------------------------
// K4: fused rescale + AV, split-K=2. Reads p_unnorm, applies per-chunk scalar
// f = exp(m_chunk - M)/S (ONE exp per 128 cols), writes normalized attention
// in place, accumulates p@V into split-K partial g_OVp{0,1}.
// 128x64 tile, 128 threads, 8x8/thread, double-buffered smem.
// NOTE: __launch_bounds__(128, 4) — the (128,8) variant capped regs at 64 and
// spilled everything to local (R10 disaster). 4 blocks/SM allows 128 regs.
// ---------------------------------------------------------------------------
__global__ void __launch_bounds__(128, 4) sav_kernel(float* __restrict__ attn)
{
    __shared__ float As[2][16][128];   // [buf][k][m]
    __shared__ float Vs[2][16][64];    // [buf][k][n]

    const int t    = threadIdx.x;
    const int tx   = t & 7;
    const int ty   = t >> 3;
    const int b    = blockIdx.y;
    const int m0   = blockIdx.x * 128;
    const int z    = blockIdx.z;           // split-K half
    const int kbeg = z * (Pp / 2);
    const int kend = kbeg + (Pp / 2);

    float* Arow = attn + (size_t)b * Pp * Pp + (size_t)(m0 + t) * Pp;
    const float* Vg = g_V + (size_t)b * Pp * HDim;
    const float2* prow = reinterpret_cast<const float2*>(g_pstat)
                       + ((size_t)b * Pp + m0 + t) * NCH;

    const float2 ms = reinterpret_cast<const float2*>(g_ms)[(size_t)b * Pp + m0 + t];
    const float myM = ms.x;
    const float myI = ms.y;

    const int vk0 = t >> 4,         vc0 = (t & 15) * 4;
    const int vk1 = (t + 128) >> 4, vc1 = ((t + 128) & 15) * 4;

    float acc[8][8];
#pragma unroll
    for (int i = 0; i < 8; i++)
#pragma unroll
        for (int j = 0; j < 8; j++) acc[i][j] = 0.f;

    float4 ra[4], rv0, rv1;
#pragma unroll
    for (int j = 0; j < 4; j++)
        ra[j] = *reinterpret_cast<const float4*>(Arow + kbeg + j * 4);
    rv0 = *reinterpret_cast<const float4*>(Vg + (size_t)(kbeg + vk0) * HDim + vc0);
    rv1 = *reinterpret_cast<const float4*>(Vg + (size_t)(kbeg + vk1) * HDim + vc1);

    // Fill stage 0
    {
        float2 pc = prow[kbeg >> 7];
        float f = __expf(pc.x - myM) * myI;
#pragma unroll
        for (int j = 0; j < 4; j++) {
            float4 p = {ra[j].x * f, ra[j].y * f, ra[j].z * f, ra[j].w * f};
            As[0][j * 4 + 0][t] = p.x; As[0][j * 4 + 1][t] = p.y;
            As[0][j * 4 + 2][t] = p.z; As[0][j * 4 + 3][t] = p.w;
            *reinterpret_cast<float4*>(Arow + kbeg + j * 4) = p;
        }
    }
    *reinterpret_cast<float4*>(&Vs[0][vk0][vc0]) = rv0;
    *reinterpret_cast<float4*>(&Vs[0][vk1][vc1]) = rv1;
    __syncthreads();

    int buf = 0;
#pragma unroll 1
    for (int kc = kbeg; kc < kend; kc += 16) {
        const bool more = (kc + 16 < kend);
        if (more) {   // prefetch next stage into registers
#pragma unroll
            for (int j = 0; j < 4; j++)
                ra[j] = *reinterpret_cast<const float4*>(Arow + kc + 16 + j * 4);
            rv0 = *reinterpret_cast<const float4*>(Vg + (size_t)(kc + 16 + vk0) * HDim + vc0);
            rv1 = *reinterpret_cast<const float4*>(Vg + (size_t)(kc + 16 + vk1) * HDim + vc1);
        }

#pragma unroll
        for (int k = 0; k < 16; k++) {
            float4 a0 = *reinterpret_cast<const float4*>(&As[buf][k][ty * 4]);
            float4 a1 = *reinterpret_cast<const float4*>(&As[buf][k][ty * 4 + 64]);
            float4 v0 = *reinterpret_cast<const float4*>(&Vs[buf][k][tx * 4]);
            float4 v1 = *reinterpret_cast<const float4*>(&Vs[buf][k][tx * 4 + 32]);
            float a[8] = {a0.x, a0.y, a0.z, a0.w, a1.x, a1.y, a1.z, a1.w};
            float v[8] = {v0.x, v0.y, v0.z, v0.w, v1.x, v1.y, v1.z, v1.w};
#pragma unroll
            for (int i = 0; i < 8; i++)
#pragma unroll
                for (int j = 0; j < 8; j++) acc[i][j] = fmaf(a[i], v[j], acc[i][j]);
        }

        if (more) {
            const int nb = buf ^ 1;
            float2 pc = prow[(kc + 16) >> 7];
            float f = __expf(pc.x - myM) * myI;
#pragma unroll
            for (int j = 0; j < 4; j++) {
                float4 p = {ra[j].x * f, ra[j].y * f, ra[j].z * f, ra[j].w * f};
                As[nb][j * 4 + 0][t] = p.x; As[nb][j * 4 + 1][t] = p.y;
                As[nb][j * 4 + 2][t] = p.z; As[nb][j * 4 + 3][t] = p.w;
                *reinterpret_cast<float4*>(Arow + kc + 16 + j * 4) = p;
            }
            *reinterpret_cast<float4*>(&Vs[nb][vk0][vc0]) = rv0;
            *reinterpret_cast<float4*>(&Vs[nb][vk1][vc1]) = rv1;
        }
        __syncthreads();
        buf ^= 1;
    }

    float* OVp = (z == 0) ? g_OVp0 : g_OVp1;
    const int n = b >> 3, h = b & 7;
#pragma unroll
    for (int i = 0; i < 8; i++) {
        int p = m0 + ty * 4 + (i & 3) + (i >> 2) * 64;
        float* dst = OVp + ((size_t)n * Pp + p) * Dd + h * HDim;
        float4 w0 = {acc[i][0], acc[i][1], acc[i][2], acc[i][3]};
        float4 w1 = {acc[i][4], acc[i][5], acc[i][6], acc[i][7]};
        *reinterpret_cast<float4*>(dst + tx * 4)      = w0;
        *reinterpret_cast<float4*>(dst + tx * 4 + 32) = w1;
    }
}

// ---------------------------------------------------------------------------
// K5: out = (OVp0+OVp1) @ Wo^T + bo. Split-K partials summed during load.
// ---------------------------------------------------------------------------
__global__ void __launch_bounds__(256) wo_kernel(
    float* __restrict__ out,
    const float* __restrict__ Wo,
    const float* __restrict__ bo)
{
    __shared__ float Xs[16][128];
    __shared__ float Ws[16][128];

    const int t   = threadIdx.x;
    const int tx  = t & 15;
    const int ty  = t >> 4;
    const int m0  = blockIdx.y * 128;
    const int n0  = blockIdx.x * 128;
    const int lr  = t & 127;
    const bool isX = (t < 128);

    const float* srcA = isX ? g_OVp0 + (size_t)(m0 + lr) * Dd
                            : Wo     + (size_t)(n0 + lr) * Dd;
    const float* srcB = g_OVp1 + (size_t)(m0 + lr) * Dd;   // used only when isX
    float (*S)[128] = isX ? Xs : Ws;

    float acc[8][8];
#pragma unroll
    for (int i = 0; i < 8; i++)
#pragma unroll
        for (int j = 0; j < 8; j++) acc[i][j] = 0.f;

    float4 rg[4];
#pragma unroll
    for (int j = 0; j < 4; j++) {
        rg[j] = *reinterpret_cast<const float4*>(srcA + j * 4);
        if (isX) {
            float4 e = *reinterpret_cast<const float4*>(srcB + j * 4);
            rg[j].x += e.x; rg[j].y += e.y; rg[j].z += e.z; rg[j].w += e.w;
        }
    }

#pragma unroll 1
    for (int kc = 0; kc < Dd; kc += 16) {
#pragma unroll
        for (int j = 0; j < 4; j++) {
            S[j * 4 + 0][lr] = rg[j].x; S[j * 4 + 1][lr] = rg[j].y;
            S[j * 4 + 2][lr] = rg[j].z; S[j * 4 + 3][lr] = rg[j].w;
        }
        __syncthreads();

        if (kc + 16 < Dd) {
#pragma unroll
            for (int j = 0; j < 4; j++) {
                rg[j] = *reinterpret_cast<const float4*>(srcA + kc + 16 + j * 4);
                if (isX) {
                    float4 e = *reinterpret_cast<const float4*>(srcB + kc + 16 + j * 4);
                    rg[j].x += e.x; rg[j].y += e.y; rg[j].z += e.z; rg[j].w += e.w;
                }
            }
        }

#pragma unroll
        for (int k = 0; k < 16; k++) {
            float4 a0 = *reinterpret_cast<const float4*>(&Xs[k][ty * 4]);
            float4 a1 = *reinterpret_cast<const float4*>(&Xs[k][ty * 4 + 64]);
            float4 w0 = *reinterpret_cast<const float4*>(&Ws[k][tx * 4]);
            float4 w1 = *reinterpret_cast<const float4*>(&Ws[k][tx * 4 + 64]);
            float a[8] = {a0.x, a0.y, a0.z, a0.w, a1.x, a1.y, a1.z, a1.w};
            float w[8] = {w0.x, w0.y, w0.z, w0.w, w1.x, w1.y, w1.z, w1.w};
#pragma unroll
            for (int i = 0; i < 8; i++)
#pragma unroll
                for (int j = 0; j < 8; j++) acc[i][j] = fmaf(a[i], w[j], acc[i][j]);
        }
        __syncthreads();
    }

    float bv[8];
#pragma unroll
    for (int j = 0; j < 8; j++)
        bv[j] = bo[n0 + tx * 4 + (j & 3) + (j >> 2) * 64];

#pragma unroll
    for (int i = 0; i < 8; i++) {
        int r = m0 + ty * 4 + (i & 3) + (i >> 2) * 64;
        float4 w0 = {acc[i][0] + bv[0], acc[i][1] + bv[1], acc[i][2] + bv[2], acc[i][3] + bv[3]};
        float4 w1 = {acc[i][4] + bv[4], acc[i][5] + bv[5], acc[i][6] + bv[6], acc[i][7] + bv[7]};
        *reinterpret_cast<float4*>(out + (size_t)r * Dd + n0 + tx * 4)      = w0;
        *reinterpret_cast<float4*>(out + (size_t)r * Dd + n0 + tx * 4 + 64) = w1;
    }
}

// ---------------------------------------------------------------------------
// Launch
// ---------------------------------------------------------------------------
extern "C" void kernel_launch(void* const* d_in, const int* in_sizes, int n_in,
                              void* d_out, int out_size)
{
    const float* xyz = (const float*)d_in[0];
    const float* Wq  = (const float*)d_in[1];
    const float* Wk  = (const float*)d_in[2];
    const float* Wv  = (const float*)d_in[3];
    const float* Wo  = (const float*)d_in[4];
    const float* bo  = (const float*)d_in[5];
    float* out = (float*)d_out;

    const size_t OUT_E  = (size_t)Nn * Pp * Dd;
    const size_t ATTN_E = (size_t)NB * Pp * Pp;

    float* attn;
    if ((size_t)out_size >= OUT_E + ATTN_E) {
        attn = out + OUT_E;
    } else {
        void* p = nullptr;
        cudaGetSymbolAddress(&p, g_attn_fb);
        attn = (float*)p;
    }

    qkv_kernel<<<(Nn * Pp * Hh) / 64, 256>>>(xyz, Wq, Wk, Wv);

    dim3 g2(Pp / 128, Pp / 128, NB);          // (16,16,32)
    qk_kernel<<<g2, 256>>>(attn);

    stat_reduce_kernel<<<(NB * Pp) / 256, 256>>>();

    dim3 g4(Pp / 128, NB, 2);                 // (16,32,2) split-K
    sav_kernel<<<g4, 128>>>(attn);

    dim3 g5(Dd / 128, (Nn * Pp) / 128);       // (4,64)
    wo_kernel<<<g5, 256>>>(out, Wo, bo);
}

// round 13
// speedup vs baseline: 3.2307x; 1.0373x over previous
#include <cuda_runtime.h>

// Problem constants
#define Nn   4
#define Pp   2048
#define Dd   512
#define Hh   8
#define HDim 64
#define NB   (Nn * Hh)                   // 32 batched (n,h) heads
#define NCH  16                          // 2048/128 col chunks in qk
#define SCALE 0.044194173824159216f      // 1/sqrt(512)

// ---------------------------------------------------------------------------
// Device scratch
// ---------------------------------------------------------------------------
__device__ float g_Q[(size_t)NB * Pp * HDim];
__device__ float g_K[(size_t)NB * Pp * HDim];
__device__ float g_V[(size_t)NB * Pp * HDim];
__device__ float g_OV[(size_t)Nn * Pp * Dd];
__device__ float g_pstat[(size_t)NB * Pp * NCH * 2];  // per (b,row,chunk): {max, sumexp}
__device__ float g_ms[(size_t)NB * Pp * 2];           // per (b,row): {max, 1/sum}
__device__ float g_attn_fb[(size_t)NB * Pp * Pp];     // fallback attention buffer

// ---------------------------------------------------------------------------
// K1: fused Q/K/V projection.
// ---------------------------------------------------------------------------
__global__ void __launch_bounds__(256) qkv_kernel(
    const float* __restrict__ x,
    const float* __restrict__ Wq,
    const float* __restrict__ Wk,
    const float* __restrict__ Wv)
{
    __shared__ float Xs[64][64];
    __shared__ float Ws[64][65];

    const int t  = threadIdx.x;
    const int tx = t & 15;
    const int ty = t >> 4;
    const int r0 = blockIdx.x * 64;

    {
        const float4* src = reinterpret_cast<const float4*>(x) + (size_t)r0 * 16;
        float4* dst = reinterpret_cast<float4*>(&Xs[0][0]);
#pragma unroll
        for (int l = 0; l < 4; l++) dst[t + 256 * l] = src[t + 256 * l];
    }

#pragma unroll 1
    for (int m = 0; m < 3; m++) {
        const float* W = (m == 0) ? Wq : (m == 1) ? Wk : Wv;
        float*       O = (m == 0) ? g_Q : (m == 1) ? g_K : g_V;

        __syncthreads();
#pragma unroll
        for (int l = 0; l < 16; l++) {
            int i = t + 256 * l;
            Ws[i >> 6][i & 63] = W[i];
        }
        __syncthreads();

        float acc[4][4];
#pragma unroll
        for (int i = 0; i < 4; i++)
#pragma unroll
            for (int j = 0; j < 4; j++) acc[i][j] = 0.f;

#pragma unroll 8
        for (int k = 0; k < 64; k++) {
            float a[4], w[4];
#pragma unroll
            for (int i = 0; i < 4; i++) a[i] = Xs[ty + 16 * i][k];
#pragma unroll
            for (int j = 0; j < 4; j++) w[j] = Ws[tx + 16 * j][k];
#pragma unroll
            for (int i = 0; i < 4; i++)
#pragma unroll
                for (int j = 0; j < 4; j++) acc[i][j] = fmaf(a[i], w[j], acc[i][j]);
        }

#pragma unroll
        for (int i = 0; i < 4; i++) {
            int r = r0 + ty + 16 * i;
            int h = r & 7;
            int p = (r >> 3) & (Pp - 1);
            int n = r >> 14;
            float* dst = O + ((size_t)(n * Hh + h) * Pp + p) * HDim;
#pragma unroll
            for (int j = 0; j < 4; j++) dst[tx + 16 * j] = acc[i][j];
        }
    }
}

// ---------------------------------------------------------------------------
// K2: energy e = (SCALE*Q) @ K^T, single-stage smem (full K=64 resident, ONE
// sync), then in registers: per-(row,chunk) max, p_unnorm = exp(e-m), partial
// sum. Stores p_unnorm to attn and {m,s} to g_pstat.
// ---------------------------------------------------------------------------
__global__ void __launch_bounds__(256) qk_kernel(float* __restrict__ attn)
{
    __shared__ float Qs[64][128];   // [k][m]  32KB
    __shared__ float Ks[64][128];   // [k][n]  32KB

    const int t    = threadIdx.x;
    const int tx   = t & 15;
    const int ty   = t >> 4;
    const int row  = t & 127;       // load row
    const int half = t >> 7;        // k-half: 0 -> k 0..31, 1 -> k 32..63
    const int b    = blockIdx.z;
    const int m0   = blockIdx.y * 128;
    const int n0   = blockIdx.x * 128;

    const float* Qg = g_Q + (size_t)b * Pp * HDim + (size_t)(m0 + row) * HDim + half * 32;
    const float* Kg = g_K + (size_t)b * Pp * HDim + (size_t)(n0 + row) * HDim + half * 32;

    // Load the full 128x64 Q and K tiles, transposed to k-major.
#pragma unroll
    for (int j = 0; j < 8; j++) {
        float4 q4 = *reinterpret_cast<const float4*>(Qg + j * 4);
        float4 k4 = *reinterpret_cast<const float4*>(Kg + j * 4);
        int kk = half * 32 + j * 4;
        Qs[kk + 0][row] = q4.x * SCALE; Qs[kk + 1][row] = q4.y * SCALE;
        Qs[kk + 2][row] = q4.z * SCALE; Qs[kk + 3][row] = q4.w * SCALE;
        Ks[kk + 0][row] = k4.x; Ks[kk + 1][row] = k4.y;
        Ks[kk + 2][row] = k4.z; Ks[kk + 3][row] = k4.w;
    }
    __syncthreads();

    float acc[8][8];
#pragma unroll
    for (int i = 0; i < 8; i++)
#pragma unroll
        for (int j = 0; j < 8; j++) acc[i][j] = 0.f;

#pragma unroll 16
    for (int k = 0; k < 64; k++) {
        float4 a0 = *reinterpret_cast<const float4*>(&Qs[k][ty * 4]);
        float4 a1 = *reinterpret_cast<const float4*>(&Qs[k][ty * 4 + 64]);
        float4 b0 = *reinterpret_cast<const float4*>(&Ks[k][tx * 4]);
        float4 b1 = *reinterpret_cast<const float4*>(&Ks[k][tx * 4 + 64]);
        float a[8]  = {a0.x, a0.y, a0.z, a0.w, a1.x, a1.y, a1.z, a1.w};
        float bb[8] = {b0.x, b0.y, b0.z, b0.w, b1.x, b1.y, b1.z, b1.w};
#pragma unroll
        for (int i = 0; i < 8; i++)
#pragma unroll
            for (int j = 0; j < 8; j++) acc[i][j] = fmaf(a[i], bb[j], acc[i][j]);
    }

    float* dst = attn + (size_t)b * Pp * Pp;
#pragma unroll
    for (int i = 0; i < 8; i++) {
        const int r = m0 + ty * 4 + (i & 3) + (i >> 2) * 64;

        // chunk-row max over the 128 cols held by the 16 tx-lanes of this ty
        float m_l = acc[i][0];
#pragma unroll
        for (int j = 1; j < 8; j++) m_l = fmaxf(m_l, acc[i][j]);
#pragma unroll
        for (int o = 8; o > 0; o >>= 1)
            m_l = fmaxf(m_l, __shfl_xor_sync(0xffffffffu, m_l, o));

        // exp in place + partial sum
        float s_l = 0.f;
#pragma unroll
        for (int j = 0; j < 8; j++) {
            acc[i][j] = __expf(acc[i][j] - m_l);
            s_l += acc[i][j];
        }
#pragma unroll
        for (int o = 8; o > 0; o >>= 1)
            s_l += __shfl_xor_sync(0xffffffffu, s_l, o);

        if (tx == 0) {
            float2* ps = reinterpret_cast<float2*>(g_pstat)
                       + ((size_t)b * Pp + r) * NCH + blockIdx.x;
            *ps = make_float2(m_l, s_l);
        }

        float4 v0 = {acc[i][0], acc[i][1], acc[i][2], acc[i][3]};
        float4 v1 = {acc[i][4], acc[i][5], acc[i][6], acc[i][7]};
        *reinterpret_cast<float4*>(dst + (size_t)r * Pp + n0 + tx * 4)      = v0;
        *reinterpret_cast<float4*>(dst + (size_t)r * Pp + n0 + tx * 4 + 64) = v1;
    }
}

// ---------------------------------------------------------------------------
// K3: merge 16 chunk partials per row -> {max, 1/sum}. 65536 rows.
// ---------------------------------------------------------------------------
__global__ void __launch_bounds__(256) stat_reduce_kernel()
{
    const int r = blockIdx.x * 256 + threadIdx.x;
    const float2* ps = reinterpret_cast<const float2*>(g_pstat) + (size_t)r * NCH;
    float m = -1e30f, s = 0.f;
#pragma unroll
    for (int c = 0; c < NCH; c++) {
        float2 v = ps[c];
        float mn = fmaxf(m, v.x);
        s = s * __expf(m - mn) + v.y * __expf(v.x - mn);
        m = mn;
    }
    reinterpret_cast<float2*>(g_ms)[r] = make_float2(m, 1.0f / s);
}

// ---------------------------------------------------------------------------
// K4: fused rescale + AV (NO split-K: 512 blocks, single wave at 4/SM).
// Reads p_unnorm, applies per-chunk scalar f = exp(m_chunk - M)/S (one exp
// per 8 stages), writes normalized attention in place, accumulates p@V.
// 128x64 tile, 128 threads, 8x8/thread, double-buffered smem.
// ---------------------------------------------------------------------------
__global__ void __launch_bounds__(128, 4) sav_kernel(float* __restrict__ attn)
{
    __shared__ float As[2][16][128];   // [buf][k][m]
    __shared__ float Vs[2][16][64];    // [buf][k][n]

    const int t    = threadIdx.x;
    const int tx   = t & 7;
    const int ty   = t >> 3;
    const int b    = blockIdx.y;
    const int m0   = blockIdx.x * 128;

    float* Arow = attn + (size_t)b * Pp * Pp + (size_t)(m0 + t) * Pp;
    const float* Vg = g_V + (size_t)b * Pp * HDim;
    const float2* prow = reinterpret_cast<const float2*>(g_pstat)
                       + ((size_t)b * Pp + m0 + t) * NCH;

    const float2 ms = reinterpret_cast<const float2*>(g_ms)[(size_t)b * Pp + m0 + t];
    const float myM = ms.x;
    const float myI = ms.y;

    const int vk0 = t >> 4,         vc0 = (t & 15) * 4;
    const int vk1 = (t + 128) >> 4, vc1 = ((t + 128) & 15) * 4;

    float acc[8][8];
#pragma unroll
    for (int i = 0; i < 8; i++)
#pragma unroll
        for (int j = 0; j < 8; j++) acc[i][j] = 0.f;

    float4 ra[4], rv0, rv1;
#pragma unroll
    for (int j = 0; j < 4; j++)
        ra[j] = *reinterpret_cast<const float4*>(Arow + j * 4);
    rv0 = *reinterpret_cast<const float4*>(Vg + (size_t)vk0 * HDim + vc0);
    rv1 = *reinterpret_cast<const float4*>(Vg + (size_t)vk1 * HDim + vc1);

    // per-chunk rescale factor, refreshed at 128-col chunk crossings
    float f = __expf(prow[0].x - myM) * myI;

    // Fill stage 0
#pragma unroll
    for (int j = 0; j < 4; j++) {
        float4 p = {ra[j].x * f, ra[j].y * f, ra[j].z * f, ra[j].w * f};
        As[0][j * 4 + 0][t] = p.x; As[0][j * 4 + 1][t] = p.y;
        As[0][j * 4 + 2][t] = p.z; As[0][j * 4 + 3][t] = p.w;
        *reinterpret_cast<float4*>(Arow + j * 4) = p;
    }
    *reinterpret_cast<float4*>(&Vs[0][vk0][vc0]) = rv0;
    *reinterpret_cast<float4*>(&Vs[0][vk1][vc1]) = rv1;
    __syncthreads();

    int buf = 0;
    int cur_ch = 0;
#pragma unroll 1
    for (int kc = 0; kc < Pp; kc += 16) {
        const bool more = (kc + 16 < Pp);
        if (more) {   // prefetch next stage into registers
#pragma unroll
            for (int j = 0; j < 4; j++)
                ra[j] = *reinterpret_cast<const float4*>(Arow + kc + 16 + j * 4);
            rv0 = *reinterpret_cast<const float4*>(Vg + (size_t)(kc + 16 + vk0) * HDim + vc0);
            rv1 = *reinterpret_cast<const float4*>(Vg + (size_t)(kc + 16 + vk1) * HDim + vc1);
        }

#pragma unroll
        for (int k = 0; k < 16; k++) {
            float4 a0 = *reinterpret_cast<const float4*>(&As[buf][k][ty * 4]);
            float4 a1 = *reinterpret_cast<const float4*>(&As[buf][k][ty * 4 + 64]);
            float4 v0 = *reinterpret_cast<const float4*>(&Vs[buf][k][tx * 4]);
            float4 v1 = *reinterpret_cast<const float4*>(&Vs[buf][k][tx * 4 + 32]);
            float a[8] = {a0.x, a0.y, a0.z, a0.w, a1.x, a1.y, a1.z, a1.w};
            float v[8] = {v0.x, v0.y, v0.z, v0.w, v1.x, v1.y, v1.z, v1.w};
#pragma unroll
            for (int i = 0; i < 8; i++)
#pragma unroll
                for (int j = 0; j < 8; j++) acc[i][j] = fmaf(a[i], v[j], acc[i][j]);
        }

        if (more) {
            const int nb = buf ^ 1;
            const int ch = (kc + 16) >> 7;
            if (ch != cur_ch) {                 // chunk crossing: refresh f
                cur_ch = ch;
                f = __expf(prow[ch].x - myM) * myI;
            }
#pragma unroll
            for (int j = 0; j < 4; j++) {
                float4 p = {ra[j].x * f, ra[j].y * f, ra[j].z * f, ra[j].w * f};
                As[nb][j * 4 + 0][t] = p.x; As[nb][j * 4 + 1][t] = p.y;
                As[nb][j * 4 + 2][t] = p.z; As[nb][j * 4 + 3][t] = p.w;
                *reinterpret_cast<float4*>(Arow + kc + 16 + j * 4) = p;
            }
            *reinterpret_cast<float4*>(&Vs[nb][vk0][vc0]) = rv0;
            *reinterpret_cast<float4*>(&Vs[nb][vk1][vc1]) = rv1;
        }
        __syncthreads();
        buf ^= 1;
    }

    const int n = b >> 3, h = b & 7;
#pragma unroll
    for (int i = 0; i < 8; i++) {
        int p = m0 + ty * 4 + (i & 3) + (i >> 2) * 64;
        float* dst = g_OV + ((size_t)n * Pp + p) * Dd + h * HDim;
        float4 w0 = {acc[i][0], acc[i][1], acc[i][2], acc[i][3]};
        float4 w1 = {acc[i][4], acc[i][5], acc[i][6], acc[i][7]};
        *reinterpret_cast<float4*>(dst + tx * 4)      = w0;
        *reinterpret_cast<float4*>(dst + tx * 4 + 32) = w1;
    }
}

// ---------------------------------------------------------------------------
// K5: out = g_OV (8192x512) @ Wo^T + bo.
// ---------------------------------------------------------------------------
__global__ void __launch_bounds__(256) wo_kernel(
    float* __restrict__ out,
    const float* __restrict__ Wo,
    const float* __restrict__ bo)
{
    __shared__ float Xs[16][128];
    __shared__ float Ws[16][128];

    const int t   = threadIdx.x;
    const int tx  = t & 15;
    const int ty  = t >> 4;
    const int m0  = blockIdx.y * 128;
    const int n0  = blockIdx.x * 128;
    const int lr  = t & 127;
    const bool isX = (t < 128);

    const float* src = isX ? g_OV + (size_t)(m0 + lr) * Dd
                           : Wo   + (size_t)(n0 + lr) * Dd;
    float (*S)[128] = isX ? Xs : Ws;

    float acc[8][8];
#pragma unroll
    for (int i = 0; i < 8; i++)
#pragma unroll
        for (int j = 0; j < 8; j++) acc[i][j] = 0.f;

    float4 rg[4];
#pragma unroll
    for (int j = 0; j < 4; j++)
        rg[j] = *reinterpret_cast<const float4*>(src + j * 4);

#pragma unroll 1
    for (int kc = 0; kc < Dd; kc += 16) {
#pragma unroll
        for (int j = 0; j < 4; j++) {
            S[j * 4 + 0][lr] = rg[j].x; S[j * 4 + 1][lr] = rg[j].y;
            S[j * 4 + 2][lr] = rg[j].z; S[j * 4 + 3][lr] = rg[j].w;
        }
        __syncthreads();

        if (kc + 16 < Dd) {
#pragma unroll
            for (int j = 0; j < 4; j++)
                rg[j] = *reinterpret_cast<const float4*>(src + kc + 16 + j * 4);
        }

#pragma unroll
        for (int k = 0; k < 16; k++) {
            float4 a0 = *reinterpret_cast<const float4*>(&Xs[k][ty * 4]);
            float4 a1 = *reinterpret_cast<const float4*>(&Xs[k][ty * 4 + 64]);
            float4 w0 = *reinterpret_cast<const float4*>(&Ws[k][tx * 4]);
            float4 w1 = *reinterpret_cast<const float4*>(&Ws[k][tx * 4 + 64]);
            float a[8] = {a0.x, a0.y, a0.z, a0.w, a1.x, a1.y, a1.z, a1.w};
            float w[8] = {w0.x, w0.y, w0.z, w0.w, w1.x, w1.y, w1.z, w1.w};
#pragma unroll
            for (int i = 0; i < 8; i++)
#pragma unroll
                for (int j = 0; j < 8; j++) acc[i][j] = fmaf(a[i], w[j], acc[i][j]);
        }
        __syncthreads();
    }

    float bv[8];
#pragma unroll
    for (int j = 0; j < 8; j++)
        bv[j] = bo[n0 + tx * 4 + (j & 3) + (j >> 2) * 64];

#pragma unroll
    for (int i = 0; i < 8; i++) {
        int r = m0 + ty * 4 + (i & 3) + (i >> 2) * 64;
        float4 w0 = {acc[i][0] + bv[0], acc[i][1] + bv[1], acc[i][2] + bv[2], acc[i][3] + bv[3]};
        float4 w1 = {acc[i][4] + bv[4], acc[i][5] + bv[5], acc[i][6] + bv[6], acc[i][7] + bv[7]};
        *reinterpret_cast<float4*>(out + (size_t)r * Dd + n0 + tx * 4)      = w0;
        *reinterpret_cast<float4*>(out + (size_t)r * Dd + n0 + tx * 4 + 64) = w1;
    }
}

// ---------------------------------------------------------------------------
// Launch
// ---------------------------------------------------------------------------
extern "C" void kernel_launch(void* const* d_in, const int* in_sizes, int n_in,
                              void* d_out, int out_size)
{
    const float* xyz = (const float*)d_in[0];
    const float* Wq  = (const float*)d_in[1];
    const float* Wk  = (const float*)d_in[2];
    const float* Wv  = (const float*)d_in[3];
    const float* Wo  = (const float*)d_in[4];
    const float* bo  = (const float*)d_in[5];
    float* out = (float*)d_out;

    const size_t OUT_E  = (size_t)Nn * Pp * Dd;
    const size_t ATTN_E = (size_t)NB * Pp * Pp;

    float* attn;
    if ((size_t)out_size >= OUT_E + ATTN_E) {
        attn = out + OUT_E;
    } else {
        void* p = nullptr;
        cudaGetSymbolAddress(&p, g_attn_fb);
        attn = (float*)p;
    }

    qkv_kernel<<<(Nn * Pp * Hh) / 64, 256>>>(xyz, Wq, Wk, Wv);

    dim3 g2(Pp / 128, Pp / 128, NB);          // (16,16,32)
    qk_kernel<<<g2, 256>>>(attn);

    stat_reduce_kernel<<<(NB * Pp) / 256, 256>>>();

    dim3 g4(Pp / 128, NB);                    // (16,32) no split-K
    sav_kernel<<<g4, 128>>>(attn);

    dim3 g5(Dd / 128, (Nn * Pp) / 128);       // (4,64)
    wo_kernel<<<g5, 256>>>(out, Wo, bo);
}

// round 16
// speedup vs baseline: 3.7467x; 1.1597x over previous
#include <cuda_runtime.h>
#include <cstdint>

// Problem constants
#define Nn   4
#define Pp   2048
#define Dd   512
#define Hh   8
#define HDim 64
#define NB   (Nn * Hh)                   // 32 batched (n,h) heads
#define NCH  16                          // 2048/128 col chunks in qk
#define SCALE 0.044194173824159216f      // 1/sqrt(512)

// ---------------------------------------------------------------------------
// Device scratch
// ---------------------------------------------------------------------------
__device__ float g_Q[(size_t)NB * Pp * HDim];
__device__ float g_K[(size_t)NB * Pp * HDim];
__device__ float g_V[(size_t)NB * Pp * HDim];
__device__ float g_OV[(size_t)Nn * Pp * Dd];
__device__ float g_pstat[(size_t)NB * Pp * NCH * 2];  // per (b,row,chunk): {max, sumexp}
__device__ float g_ms[(size_t)NB * Pp * 2];           // per (b,row): {max, 1/sum}
__device__ float g_attn_fb[(size_t)NB * Pp * Pp];     // fallback attention buffer

// ---------------------------------------------------------------------------
// tf32 helpers
// ---------------------------------------------------------------------------
__device__ __forceinline__ uint32_t f2tf32(float x) {
    uint32_t u;
    asm("cvt.rna.tf32.f32 %0, %1;" : "=r"(u) : "f"(x));
    return u;
}

__device__ __forceinline__ void mma_tf32(float* c, const uint32_t* a,
                                         uint32_t b0, uint32_t b1) {
    asm volatile(
        "mma.sync.aligned.m16n8k8.row.col.f32.tf32.tf32.f32 "
        "{%0,%1,%2,%3}, {%4,%5,%6,%7}, {%8,%9}, {%0,%1,%2,%3};"
        : "+f"(c[0]), "+f"(c[1]), "+f"(c[2]), "+f"(c[3])
        : "r"(a[0]), "r"(a[1]), "r"(a[2]), "r"(a[3]), "r"(b0), "r"(b1));
}

// ---------------------------------------------------------------------------
// K1: fused Q/K/V projection (unchanged).
// ---------------------------------------------------------------------------
__global__ void __launch_bounds__(256) qkv_kernel(
    const float* __restrict__ x,
    const float* __restrict__ Wq,
    const float* __restrict__ Wk,
    const float* __restrict__ Wv)
{
    __shared__ float Xs[64][64];
    __shared__ float Ws[64][65];

    const int t  = threadIdx.x;
    const int tx = t & 15;
    const int ty = t >> 4;
    const int r0 = blockIdx.x * 64;

    {
        const float4* src = reinterpret_cast<const float4*>(x) + (size_t)r0 * 16;
        float4* dst = reinterpret_cast<float4*>(&Xs[0][0]);
#pragma unroll
        for (int l = 0; l < 4; l++) dst[t + 256 * l] = src[t + 256 * l];
    }

#pragma unroll 1
    for (int m = 0; m < 3; m++) {
        const float* W = (m == 0) ? Wq : (m == 1) ? Wk : Wv;
        float*       O = (m == 0) ? g_Q : (m == 1) ? g_K : g_V;

        __syncthreads();
#pragma unroll
        for (int l = 0; l < 16; l++) {
            int i = t + 256 * l;
            Ws[i >> 6][i & 63] = W[i];
        }
        __syncthreads();

        float acc[4][4];
#pragma unroll
        for (int i = 0; i < 4; i++)
#pragma unroll
            for (int j = 0; j < 4; j++) acc[i][j] = 0.f;

#pragma unroll 8
        for (int k = 0; k < 64; k++) {
            float a[4], w[4];
#pragma unroll
            for (int i = 0; i < 4; i++) a[i] = Xs[ty + 16 * i][k];
#pragma unroll
            for (int j = 0; j < 4; j++) w[j] = Ws[tx + 16 * j][k];
#pragma unroll
            for (int i = 0; i < 4; i++)
#pragma unroll
                for (int j = 0; j < 4; j++) acc[i][j] = fmaf(a[i], w[j], acc[i][j]);
        }

#pragma unroll
        for (int i = 0; i < 4; i++) {
            int r = r0 + ty + 16 * i;
            int h = r & 7;
            int p = (r >> 3) & (Pp - 1);
            int n = r >> 14;
            float* dst = O + ((size_t)(n * Hh + h) * Pp + p) * HDim;
#pragma unroll
            for (int j = 0; j < 4; j++) dst[tx + 16 * j] = acc[i][j];
        }
    }
}

// ---------------------------------------------------------------------------
// K2: energy e = (SCALE*Q) @ K^T, single-stage smem, exp in epilogue
// (unchanged from R13).
// ---------------------------------------------------------------------------
__global__ void __launch_bounds__(256) qk_kernel(float* __restrict__ attn)
{
    __shared__ float Qs[64][128];   // [k][m]  32KB
    __shared__ float Ks[64][128];   // [k][n]  32KB

    const int t    = threadIdx.x;
    const int tx   = t & 15;
    const int ty   = t >> 4;
    const int row  = t & 127;
    const int half = t >> 7;
    const int b    = blockIdx.z;
    const int m0   = blockIdx.y * 128;
    const int n0   = blockIdx.x * 128;

    const float* Qg = g_Q + (size_t)b * Pp * HDim + (size_t)(m0 + row) * HDim + half * 32;
    const float* Kg = g_K + (size_t)b * Pp * HDim + (size_t)(n0 + row) * HDim + half * 32;

#pragma unroll
    for (int j = 0; j < 8; j++) {
        float4 q4 = *reinterpret_cast<const float4*>(Qg + j * 4);
        float4 k4 = *reinterpret_cast<const float4*>(Kg + j * 4);
        int kk = half * 32 + j * 4;
        Qs[kk + 0][row] = q4.x * SCALE; Qs[kk + 1][row] = q4.y * SCALE;
        Qs[kk + 2][row] = q4.z * SCALE; Qs[kk + 3][row] = q4.w * SCALE;
        Ks[kk + 0][row] = k4.x; Ks[kk + 1][row] = k4.y;
        Ks[kk + 2][row] = k4.z; Ks[kk + 3][row] = k4.w;
    }
    __syncthreads();

    float acc[8][8];
#pragma unroll
    for (int i = 0; i < 8; i++)
#pragma unroll
        for (int j = 0; j < 8; j++) acc[i][j] = 0.f;

#pragma unroll 16
    for (int k = 0; k < 64; k++) {
        float4 a0 = *reinterpret_cast<const float4*>(&Qs[k][ty * 4]);
        float4 a1 = *reinterpret_cast<const float4*>(&Qs[k][ty * 4 + 64]);
        float4 b0 = *reinterpret_cast<const float4*>(&Ks[k][tx * 4]);
        float4 b1 = *reinterpret_cast<const float4*>(&Ks[k][tx * 4 + 64]);
        float a[8]  = {a0.x, a0.y, a0.z, a0.w, a1.x, a1.y, a1.z, a1.w};
        float bb[8] = {b0.x, b0.y, b0.z, b0.w, b1.x, b1.y, b1.z, b1.w};
#pragma unroll
        for (int i = 0; i < 8; i++)
#pragma unroll
            for (int j = 0; j < 8; j++) acc[i][j] = fmaf(a[i], bb[j], acc[i][j]);
    }

    float* dst = attn + (size_t)b * Pp * Pp;
#pragma unroll
    for (int i = 0; i < 8; i++) {
        const int r = m0 + ty * 4 + (i & 3) + (i >> 2) * 64;

        float m_l = acc[i][0];
#pragma unroll
        for (int j = 1; j < 8; j++) m_l = fmaxf(m_l, acc[i][j]);
#pragma unroll
        for (int o = 8; o > 0; o >>= 1)
            m_l = fmaxf(m_l, __shfl_xor_sync(0xffffffffu, m_l, o));

        float s_l = 0.f;
#pragma unroll
        for (int j = 0; j < 8; j++) {
            acc[i][j] = __expf(acc[i][j] - m_l);
            s_l += acc[i][j];
        }
#pragma unroll
        for (int o = 8; o > 0; o >>= 1)
            s_l += __shfl_xor_sync(0xffffffffu, s_l, o);

        if (tx == 0) {
            float2* ps = reinterpret_cast<float2*>(g_pstat)
                       + ((size_t)b * Pp + r) * NCH + blockIdx.x;
            *ps = make_float2(m_l, s_l);
        }

        float4 v0 = {acc[i][0], acc[i][1], acc[i][2], acc[i][3]};
        float4 v1 = {acc[i][4], acc[i][5], acc[i][6], acc[i][7]};
        *reinterpret_cast<float4*>(dst + (size_t)r * Pp + n0 + tx * 4)      = v0;
        *reinterpret_cast<float4*>(dst + (size_t)r * Pp + n0 + tx * 4 + 64) = v1;
    }
}

// ---------------------------------------------------------------------------
// K3: merge 16 chunk partials per row -> {max, 1/sum}. 65536 rows.
// ---------------------------------------------------------------------------
__global__ void __launch_bounds__(256) stat_reduce_kernel()
{
    const int r = blockIdx.x * 256 + threadIdx.x;
    const float2* ps = reinterpret_cast<const float2*>(g_pstat) + (size_t)r * NCH;
    float m = -1e30f, s = 0.f;
#pragma unroll
    for (int c = 0; c < NCH; c++) {
        float2 v = ps[c];
        float mn = fmaxf(m, v.x);
        s = s * __expf(m - mn) + v.y * __expf(v.x - mn);
        m = mn;
    }
    reinterpret_cast<float2*>(g_ms)[r] = make_float2(m, 1.0f / s);
}

// ---------------------------------------------------------------------------
// K4: fused rescale + AV on the TENSOR pipe (mma.sync m16n8k8 tf32).
// Reads p_unnorm, rescales by per-chunk f (fp32), writes normalized attention
// in place (fp32 - attention output unaffected by tf32), converts p and V to
// tf32 in the smem-fill path, and runs the 128x64 @ k GEMM via HMMA.
// 128 threads = 4 warps; warp w owns rows w*32..w*32+31 (2 m16 tiles x 8 n8).
// Padding: As k-stride 136, Vs 72 (both ≡ 8 mod 32 -> conflict-free frags).
// ---------------------------------------------------------------------------
__global__ void __launch_bounds__(128, 4) sav_kernel(float* __restrict__ attn)
{
    __shared__ float As[2][16][136];   // [buf][k][m] tf32 bits, pad 136
    __shared__ float Vs[2][16][72];    // [buf][k][n] tf32 bits, pad 72

    const int t    = threadIdx.x;
    const int w    = t >> 5;           // warp id 0..3
    const int lane = t & 31;
    const int g    = lane >> 2;        // groupID (0..7)
    const int tg   = lane & 3;         // thread-in-group (0..3)
    const int b    = blockIdx.y;
    const int m0   = blockIdx.x * 128;

    float* Arow = attn + (size_t)b * Pp * Pp + (size_t)(m0 + t) * Pp;
    const float* Vg = g_V + (size_t)b * Pp * HDim;
    const float2* prow = reinterpret_cast<const float2*>(g_pstat)
                       + ((size_t)b * Pp + m0 + t) * NCH;

    const float2 ms = reinterpret_cast<const float2*>(g_ms)[(size_t)b * Pp + m0 + t];
    const float myM = ms.x;
    const float myI = ms.y;

    const int vk0 = t >> 4,         vc0 = (t & 15) * 4;
    const int vk1 = (t + 128) >> 4, vc1 = ((t + 128) & 15) * 4;

    float acc[2][8][4];                // [m16 tile][n8 tile][c0..c3]
#pragma unroll
    for (int mt = 0; mt < 2; mt++)
#pragma unroll
        for (int nt = 0; nt < 8; nt++)
#pragma unroll
            for (int c = 0; c < 4; c++) acc[mt][nt][c] = 0.f;

    float4 ra[4], rv0, rv1;
#pragma unroll
    for (int j = 0; j < 4; j++)
        ra[j] = *reinterpret_cast<const float4*>(Arow + j * 4);
    rv0 = *reinterpret_cast<const float4*>(Vg + (size_t)vk0 * HDim + vc0);
    rv1 = *reinterpret_cast<const float4*>(Vg + (size_t)vk1 * HDim + vc1);

    float f = __expf(prow[0].x - myM) * myI;

    // Fill stage 0: fp32 normalize -> STG attn; tf32 convert -> STS.
#pragma unroll
    for (int j = 0; j < 4; j++) {
        float4 p = {ra[j].x * f, ra[j].y * f, ra[j].z * f, ra[j].w * f};
        *reinterpret_cast<float4*>(Arow + j * 4) = p;
        As[0][j * 4 + 0][t] = __uint_as_float(f2tf32(p.x));
        As[0][j * 4 + 1][t] = __uint_as_float(f2tf32(p.y));
        As[0][j * 4 + 2][t] = __uint_as_float(f2tf32(p.z));
        As[0][j * 4 + 3][t] = __uint_as_float(f2tf32(p.w));
    }
    {
        uint4 v0 = {f2tf32(rv0.x), f2tf32(rv0.y), f2tf32(rv0.z), f2tf32(rv0.w)};
        uint4 v1 = {f2tf32(rv1.x), f2tf32(rv1.y), f2tf32(rv1.z), f2tf32(rv1.w)};
        *reinterpret_cast<uint4*>(&Vs[0][vk0][vc0]) = v0;
        *reinterpret_cast<uint4*>(&Vs[0][vk1][vc1]) = v1;
    }
    __syncthreads();

    int buf = 0;
    int cur_ch = 0;
#pragma unroll 1
    for (int kc = 0; kc < Pp; kc += 16) {
        const bool more = (kc + 16 < Pp);
        if (more) {   // prefetch next stage into registers
#pragma unroll
            for (int j = 0; j < 4; j++)
                ra[j] = *reinterpret_cast<const float4*>(Arow + kc + 16 + j * 4);
            rv0 = *reinterpret_cast<const float4*>(Vg + (size_t)(kc + 16 + vk0) * HDim + vc0);
            rv1 = *reinterpret_cast<const float4*>(Vg + (size_t)(kc + 16 + vk1) * HDim + vc1);
        }

        // Tensor-pipe consume: 2 k8 halves x (2 m-tiles x 8 n-tiles) HMMA
#pragma unroll
        for (int kk = 0; kk < 16; kk += 8) {
            uint32_t af[2][4];
#pragma unroll
            for (int mt = 0; mt < 2; mt++) {
                const int r0 = w * 32 + mt * 16;
                af[mt][0] = __float_as_uint(As[buf][kk + tg    ][r0 + g    ]);
                af[mt][1] = __float_as_uint(As[buf][kk + tg    ][r0 + g + 8]);
                af[mt][2] = __float_as_uint(As[buf][kk + tg + 4][r0 + g    ]);
                af[mt][3] = __float_as_uint(As[buf][kk + tg + 4][r0 + g + 8]);
            }
#pragma unroll
            for (int nt = 0; nt < 8; nt++) {
                uint32_t b0 = __float_as_uint(Vs[buf][kk + tg    ][nt * 8 + g]);
                uint32_t b1 = __float_as_uint(Vs[buf][kk + tg + 4][nt * 8 + g]);
                mma_tf32(acc[0][nt], af[0], b0, b1);
                mma_tf32(acc[1][nt], af[1], b0, b1);
            }
        }

        if (more) {
            const int nb = buf ^ 1;
            const int ch = (kc + 16) >> 7;
            if (ch != cur_ch) {                 // chunk crossing: refresh f
                cur_ch = ch;
                f = __expf(prow[ch].x - myM) * myI;
            }
#pragma unroll
            for (int j = 0; j < 4; j++) {
                float4 p = {ra[j].x * f, ra[j].y * f, ra[j].z * f, ra[j].w * f};
                *reinterpret_cast<float4*>(Arow + kc + 16 + j * 4) = p;
                As[nb][j * 4 + 0][t] = __uint_as_float(f2tf32(p.x));
                As[nb][j * 4 + 1][t] = __uint_as_float(f2tf32(p.y));
                As[nb][j * 4 + 2][t] = __uint_as_float(f2tf32(p.z));
                As[nb][j * 4 + 3][t] = __uint_as_float(f2tf32(p.w));
            }
            uint4 v0 = {f2tf32(rv0.x), f2tf32(rv0.y), f2tf32(rv0.z), f2tf32(rv0.w)};
            uint4 v1 = {f2tf32(rv1.x), f2tf32(rv1.y), f2tf32(rv1.z), f2tf32(rv1.w)};
            *reinterpret_cast<uint4*>(&Vs[nb][vk0][vc0]) = v0;
            *reinterpret_cast<uint4*>(&Vs[nb][vk1][vc1]) = v1;
        }
        __syncthreads();
        buf ^= 1;
    }

    // Epilogue: fragment layout c0:(g, tg*2) c1:(g, tg*2+1) c2:(g+8,..) c3.
    const int n = b >> 3, h = b & 7;
#pragma unroll
    for (int mt = 0; mt < 2; mt++) {
        const int r0 = m0 + w * 32 + mt * 16 + g;
#pragma unroll
        for (int nt = 0; nt < 8; nt++) {
            const int col = h * HDim + nt * 8 + tg * 2;
            float* d0 = g_OV + ((size_t)n * Pp + r0) * Dd + col;
            float* d1 = g_OV + ((size_t)n * Pp + r0 + 8) * Dd + col;
            *reinterpret_cast<float2*>(d0) = make_float2(acc[mt][nt][0], acc[mt][nt][1]);
            *reinterpret_cast<float2*>(d1) = make_float2(acc[mt][nt][2], acc[mt][nt][3]);
        }
    }
}

// ---------------------------------------------------------------------------
// K5: out = g_OV (8192x512) @ Wo^T + bo (unchanged).
// ---------------------------------------------------------------------------
__global__ void __launch_bounds__(256) wo_kernel(
    float* __restrict__ out,
    const float* __restrict__ Wo,
    const float* __restrict__ bo)
{
    __shared__ float Xs[16][128];
    __shared__ float Ws[16][128];

    const int t   = threadIdx.x;
    const int tx  = t & 15;
    const int ty  = t >> 4;
    const int m0  = blockIdx.y * 128;
    const int n0  = blockIdx.x * 128;
    const int lr  = t & 127;
    const bool isX = (t < 128);

    const float* src = isX ? g_OV + (size_t)(m0 + lr) * Dd
                           : Wo   + (size_t)(n0 + lr) * Dd;
    float (*S)[128] = isX ? Xs : Ws;

    float acc[8][8];
#pragma unroll
    for (int i = 0; i < 8; i++)
#pragma unroll
        for (int j = 0; j < 8; j++) acc[i][j] = 0.f;

    float4 rg[4];
#pragma unroll
    for (int j = 0; j < 4; j++)
        rg[j] = *reinterpret_cast<const float4*>(src + j * 4);

#pragma unroll 1
    for (int kc = 0; kc < Dd; kc += 16) {
#pragma unroll
        for (int j = 0; j < 4; j++) {
            S[j * 4 + 0][lr] = rg[j].x; S[j * 4 + 1][lr] = rg[j].y;
            S[j * 4 + 2][lr] = rg[j].z; S[j * 4 + 3][lr] = rg[j].w;
        }
        __syncthreads();

        if (kc + 16 < Dd) {
#pragma unroll
            for (int j = 0; j < 4; j++)
                rg[j] = *reinterpret_cast<const float4*>(src + kc + 16 + j * 4);
        }

#pragma unroll
        for (int k = 0; k < 16; k++) {
            float4 a0 = *reinterpret_cast<const float4*>(&Xs[k][ty * 4]);
            float4 a1 = *reinterpret_cast<const float4*>(&Xs[k][ty * 4 + 64]);
            float4 w0 = *reinterpret_cast<const float4*>(&Ws[k][tx * 4]);
            float4 w1 = *reinterpret_cast<const float4*>(&Ws[k][tx * 4 + 64]);
            float a[8] = {a0.x, a0.y, a0.z, a0.w, a1.x, a1.y, a1.z, a1.w};
            float w[8] = {w0.x, w0.y, w0.z, w0.w, w1.x, w1.y, w1.z, w1.w};
#pragma unroll
            for (int i = 0; i < 8; i++)
#pragma unroll
                for (int j = 0; j < 8; j++) acc[i][j] = fmaf(a[i], w[j], acc[i][j]);
        }
        __syncthreads();
    }

    float bv[8];
#pragma unroll
    for (int j = 0; j < 8; j++)
        bv[j] = bo[n0 + tx * 4 + (j & 3) + (j >> 2) * 64];

#pragma unroll
    for (int i = 0; i < 8; i++) {
        int r = m0 + ty * 4 + (i & 3) + (i >> 2) * 64;
        float4 w0 = {acc[i][0] + bv[0], acc[i][1] + bv[1], acc[i][2] + bv[2], acc[i][3] + bv[3]};
        float4 w1 = {acc[i][4] + bv[4], acc[i][5] + bv[5], acc[i][6] + bv[6], acc[i][7] + bv[7]};
        *reinterpret_cast<float4*>(out + (size_t)r * Dd + n0 + tx * 4)      = w0;
        *reinterpret_cast<float4*>(out + (size_t)r * Dd + n0 + tx * 4 + 64) = w1;
    }
}

// ---------------------------------------------------------------------------
// Launch
// ---------------------------------------------------------------------------
extern "C" void kernel_launch(void* const* d_in, const int* in_sizes, int n_in,
                              void* d_out, int out_size)
{
    const float* xyz = (const float*)d_in[0];
    const float* Wq  = (const float*)d_in[1];
    const float* Wk  = (const float*)d_in[2];
    const float* Wv  = (const float*)d_in[3];
    const float* Wo  = (const float*)d_in[4];
    const float* bo  = (const float*)d_in[5];
    float* out = (float*)d_out;

    const size_t OUT_E  = (size_t)Nn * Pp * Dd;
    const size_t ATTN_E = (size_t)NB * Pp * Pp;

    float* attn;
    if ((size_t)out_size >= OUT_E + ATTN_E) {
        attn = out + OUT_E;
    } else {
        void* p = nullptr;
        cudaGetSymbolAddress(&p, g_attn_fb);
        attn = (float*)p;
    }

    qkv_kernel<<<(Nn * Pp * Hh) / 64, 256>>>(xyz, Wq, Wk, Wv);

    dim3 g2(Pp / 128, Pp / 128, NB);          // (16,16,32)
    qk_kernel<<<g2, 256>>>(attn);

    stat_reduce_kernel<<<(NB * Pp) / 256, 256>>>();

    dim3 g4(Pp / 128, NB);                    // (16,32)
    sav_kernel<<<g4, 128>>>(attn);

    dim3 g5(Dd / 128, (Nn * Pp) / 128);       // (4,64)
    wo_kernel<<<g5, 256>>>(out, Wo, bo);
}